// round 4
// baseline (speedup 1.0000x reference)
#include <cuda_runtime.h>
#include <cstdint>

// Scratch: inverse permutation inv[p*load + tag] = global source row (p*T + t).
#define INV_MAX (1 << 21)
__device__ int d_inv[INV_MAX];

// Fused dtype-probe + permutation inversion (see R2/R3 notes: int32-vs-int64
// detection is deterministic per block from the first 64 int64-view words).
__global__ void invert_fused_kernel(const void* __restrict__ tags,
                                    int n, int T, int load) {
    __shared__ int s_is32;
    if (threadIdx.x == 0) s_is32 = 0;
    __syncthreads();
    int scan = n / 2 < 64 ? n / 2 : 64;
    if ((int)threadIdx.x < scan) {
        long long v = ((const long long*)tags)[threadIdx.x];
        if (v < 0 || v >= (long long)load) atomicOr(&s_is32, 1);
    }
    __syncthreads();
    bool is32 = (s_is32 != 0);

    int stride = gridDim.x * blockDim.x;
    for (int idx = blockIdx.x * blockDim.x + threadIdx.x; idx < n; idx += stride) {
        int p = idx / T;
        long long tag = is32 ? (long long)((const int*)tags)[idx]
                             : ((const long long*)tags)[idx];
        if (tag >= 0 && tag < (long long)load)
            d_inv[(long long)p * load + tag] = idx;
    }
}

// Hot kernel, specialized: P=2, Dv == 2*blockDim (Dv=512, block=256).
// Each block handles TWO output rows; each thread issues 8 independent 16B
// loads (4 source rows x 2 columns) before any arithmetic -> deep MLP.
__global__ void __launch_bounds__(256) gather_2row2_kernel(
    const float4* __restrict__ data, float4* __restrict__ out, int load, int Dv) {
    int row0 = blockIdx.x * 2;
    int row1 = row0 + 1;
    int s00 = __ldg(&d_inv[row0]);
    int s01 = __ldg(&d_inv[load + row0]);
    int s10 = __ldg(&d_inv[row1]);
    int s11 = __ldg(&d_inv[load + row1]);
    const float4* __restrict__ a0 = data + (long long)s00 * Dv;
    const float4* __restrict__ b0 = data + (long long)s01 * Dv;
    const float4* __restrict__ a1 = data + (long long)s10 * Dv;
    const float4* __restrict__ b1 = data + (long long)s11 * Dv;
    float4* __restrict__ o0 = out + (long long)row0 * Dv;
    float4* __restrict__ o1 = out + (long long)row1 * Dv;

    int t = threadIdx.x;
    int t2 = t + 256;
    // 8 independent loads in flight.
    float4 va0 = __ldcs(a0 + t);
    float4 vb0 = __ldcs(b0 + t);
    float4 va1 = __ldcs(a0 + t2);
    float4 vb1 = __ldcs(b0 + t2);
    float4 va2 = __ldcs(a1 + t);
    float4 vb2 = __ldcs(b1 + t);
    float4 va3 = __ldcs(a1 + t2);
    float4 vb3 = __ldcs(b1 + t2);

    float4 r0, r1, r2, r3;
    r0.x = va0.x + vb0.x; r0.y = va0.y + vb0.y; r0.z = va0.z + vb0.z; r0.w = va0.w + vb0.w;
    r1.x = va1.x + vb1.x; r1.y = va1.y + vb1.y; r1.z = va1.z + vb1.z; r1.w = va1.w + vb1.w;
    r2.x = va2.x + vb2.x; r2.y = va2.y + vb2.y; r2.z = va2.z + vb2.z; r2.w = va2.w + vb2.w;
    r3.x = va3.x + vb3.x; r3.y = va3.y + vb3.y; r3.z = va3.z + vb3.z; r3.w = va3.w + vb3.w;
    __stcs(o0 + t, r0);
    __stcs(o0 + t2, r1);
    __stcs(o1 + t, r2);
    __stcs(o1 + t2, r3);
}

// Single-row variant for an odd trailing row (same shape assumptions).
__global__ void __launch_bounds__(256) gather_1row2_kernel(
    const float4* __restrict__ data, float4* __restrict__ out,
    int load, int Dv, int row) {
    int s0 = __ldg(&d_inv[row]);
    int s1 = __ldg(&d_inv[load + row]);
    const float4* __restrict__ a = data + (long long)s0 * Dv;
    const float4* __restrict__ b = data + (long long)s1 * Dv;
    float4* __restrict__ o = out + (long long)row * Dv;
    for (int c = threadIdx.x; c < Dv; c += blockDim.x) {
        float4 x = __ldcs(a + c), y = __ldcs(b + c);
        float4 r;
        r.x = x.x + y.x; r.y = x.y + y.y; r.z = x.z + y.z; r.w = x.w + y.w;
        __stcs(o + c, r);
    }
}

// Generic-P fallback: block per output row.
__global__ void __launch_bounds__(256) gather_rowP_kernel(
    const float4* __restrict__ data, float4* __restrict__ out,
    int load, int Dv, int P) {
    int row = blockIdx.x;
    float4* __restrict__ o = out + (long long)row * Dv;
    for (int c = threadIdx.x; c < Dv; c += blockDim.x) {
        float4 r = make_float4(0.f, 0.f, 0.f, 0.f);
        for (int p = 0; p < P; ++p) {
            int s = __ldg(&d_inv[(long long)p * load + row]);
            float4 v = __ldcs(data + (long long)s * Dv + c);
            r.x += v.x; r.y += v.y; r.z += v.z; r.w += v.w;
        }
        __stcs(o + c, r);
    }
}

// Scalar fallback if D % 4 != 0.
__global__ void gather_rowP_scalar_kernel(
    const float* __restrict__ data, float* __restrict__ out,
    int load, int D, int P) {
    int row = blockIdx.x;
    float* __restrict__ o = out + (long long)row * D;
    for (int c = threadIdx.x; c < D; c += blockDim.x) {
        float r = 0.f;
        for (int p = 0; p < P; ++p) {
            int s = __ldg(&d_inv[(long long)p * load + row]);
            r += __ldg(data + (long long)s * D + c);
        }
        o[c] = r;
    }
}

extern "C" void kernel_launch(void* const* d_in, const int* in_sizes, int n_in,
                              void* d_out, int out_size) {
    const float* flows_data = (const float*)d_in[0];
    const void* flows_tag = d_in[1];

    int n_rows = in_sizes[1];            // P * T
    int D = in_sizes[0] / n_rows;        // feature dim
    int load = out_size / D;             // output rows (== T here)
    int P = n_rows / load;               // paths (== 2 here)
    int T = n_rows / P;                  // tokens per flow

    // Prologue: single fused probe+invert launch (tiny).
    {
        int threads = 256;
        int blocks = (n_rows + threads - 1) / threads;
        if (blocks > 64) blocks = 64;
        invert_fused_kernel<<<blocks, threads>>>(flows_tag, n_rows, T, load);
    }

    // Hot gather-sum.
    if ((D & 3) == 0) {
        int Dv = D >> 2;
        if (P == 2 && Dv == 512) {
            int pairs = load / 2;
            if (pairs > 0)
                gather_2row2_kernel<<<pairs, 256>>>(
                    (const float4*)flows_data, (float4*)d_out, load, Dv);
            if (load & 1)
                gather_1row2_kernel<<<1, 256>>>(
                    (const float4*)flows_data, (float4*)d_out, load, Dv, load - 1);
        } else {
            gather_rowP_kernel<<<load, 256>>>(
                (const float4*)flows_data, (float4*)d_out, load, Dv, P);
        }
    } else {
        gather_rowP_scalar_kernel<<<load, 256>>>(
            flows_data, (float*)d_out, load, D, P);
    }
}